// round 15
// baseline (speedup 1.0000x reference)
#include <cuda_runtime.h>
#include <cuda_bf16.h>

#define B 256
#define N 128
#define D 64

// 16 MB score scratch: score[b][i][j]
__device__ float g_score[(size_t)B * N * N];

__device__ __forceinline__ float sigmoidf_(float x) {
    return 1.0f / (1.0f + __expf(-x));
}

// -BETA * log(-GAMMA/ZETA) = -(2/3)*ln(0.1/1.1) = +1.5985968...
#define L0_SHIFT 1.5985968919582645f

__global__ void init_l0_kernel(float* out, int out_size) {
    out[out_size - 1] = 0.0f;
}

// One block per (i,j). 256 threads, thread t owns batch b = t.
__global__ void __launch_bounds__(256, 2)
score_kernel(const float* __restrict__ q,
             const float* __restrict__ k,
             const float* __restrict__ m,
             float* __restrict__ out, int l0_size)
{
    __shared__ float zs[D * D];     // 16 KB z tile, row-major [d][e]
    __shared__ float l0sm[8];

    const int ij = blockIdx.x;
    const int i  = ij >> 7;
    const int j  = ij & (N - 1);
    const int t  = threadIdx.x;

    // ---- Stage 1: load matrix tile, compute z + l0 partial ----
    const float4* mt = (const float4*)(m + (size_t)ij * (D * D));
    float4* zs4 = (float4*)zs;
    float l0p = 0.0f;
    #pragma unroll
    for (int r = 0; r < 4; r++) {
        float4 mv = __ldg(mt + t + r * 256);
        l0p += sigmoidf_(mv.x + L0_SHIFT) + sigmoidf_(mv.y + L0_SHIFT)
             + sigmoidf_(mv.z + L0_SHIFT) + sigmoidf_(mv.w + L0_SHIFT);
        float4 zv;
        zv.x = fminf(fmaxf(sigmoidf_(mv.x) * 1.2f - 0.1f, 0.0f), 1.0f);
        zv.y = fminf(fmaxf(sigmoidf_(mv.y) * 1.2f - 0.1f, 0.0f), 1.0f);
        zv.z = fminf(fmaxf(sigmoidf_(mv.z) * 1.2f - 0.1f, 0.0f), 1.0f);
        zv.w = fminf(fmaxf(sigmoidf_(mv.w) * 1.2f - 0.1f, 0.0f), 1.0f);
        zs4[t + r * 256] = zv;
    }
    // l0 block reduction -> one atomicAdd per block
    #pragma unroll
    for (int o = 16; o; o >>= 1) l0p += __shfl_xor_sync(0xFFFFFFFFu, l0p, o);
    if ((t & 31) == 0) l0sm[t >> 5] = l0p;
    __syncthreads();
    if (t == 0 && l0_size > 0) {
        float s = 0.0f;
        #pragma unroll
        for (int w = 0; w < 8; w++) s += l0sm[w];
        atomicAdd(out + (l0_size - 1), s);
    }

    // ---- Stage 2: score[b] = (q_b,i^T Z k_b,j) / sqrt(D) ----
    const int b = t;
    float qr[D];
    {
        const float4* qp = (const float4*)(q + ((size_t)b * N + i) * D);
        #pragma unroll
        for (int c = 0; c < 16; c++) {
            float4 vv = __ldg(qp + c);
            qr[4*c+0] = vv.x; qr[4*c+1] = vv.y; qr[4*c+2] = vv.z; qr[4*c+3] = vv.w;
        }
    }
    const float4* kp = (const float4*)(k + ((size_t)b * N + j) * D);

    float score = 0.0f;
    #pragma unroll 1
    for (int e0 = 0; e0 < D; e0 += 8) {
        float a0=0,a1=0,a2=0,a3=0,a4=0,a5=0,a6=0,a7=0;
        const float4* z4 = ((const float4*)zs) + (e0 >> 2);
        #pragma unroll
        for (int d = 0; d < D; d++) {
            float4 za = z4[d * 16];        // smem broadcast (all lanes same addr)
            float4 zb = z4[d * 16 + 1];
            float qd = qr[d];
            a0 = fmaf(qd, za.x, a0); a1 = fmaf(qd, za.y, a1);
            a2 = fmaf(qd, za.z, a2); a3 = fmaf(qd, za.w, a3);
            a4 = fmaf(qd, zb.x, a4); a5 = fmaf(qd, zb.y, a5);
            a6 = fmaf(qd, zb.z, a6); a7 = fmaf(qd, zb.w, a7);
        }
        float4 k0 = __ldg(kp + (e0 >> 2));
        float4 k1 = __ldg(kp + (e0 >> 2) + 1);
        score += a0*k0.x + a1*k0.y + a2*k0.z + a3*k0.w
               + a4*k1.x + a5*k1.y + a6*k1.z + a7*k1.w;
    }
    g_score[((size_t)b * N + i) * N + j] = score * 0.125f;  // 1/sqrt(64)
}

// One warp per (b,i): softmax over j then attn @ v. 4 warps/block.
__global__ void __launch_bounds__(128)
softmax_av_kernel(const float* __restrict__ v, float* __restrict__ out)
{
    const int warp = blockIdx.x * 4 + (threadIdx.x >> 5);
    const int lane = threadIdx.x & 31;
    const int w    = threadIdx.x >> 5;
    const int b = warp >> 7;
    const int i = warp & (N - 1);

    const float* s = g_score + ((size_t)b * N + i) * N;
    float sv[4];
    float mx = -1e30f;
    #pragma unroll
    for (int r = 0; r < 4; r++) { sv[r] = s[lane + 32 * r]; mx = fmaxf(mx, sv[r]); }
    #pragma unroll
    for (int o = 16; o; o >>= 1) mx = fmaxf(mx, __shfl_xor_sync(0xFFFFFFFFu, mx, o));
    float sum = 0.0f;
    #pragma unroll
    for (int r = 0; r < 4; r++) { sv[r] = __expf(sv[r] - mx); sum += sv[r]; }
    #pragma unroll
    for (int o = 16; o; o >>= 1) sum += __shfl_xor_sync(0xFFFFFFFFu, sum, o);
    const float inv = 1.0f / sum;

    __shared__ float psm[4][N];
    #pragma unroll
    for (int r = 0; r < 4; r++) psm[w][lane + 32 * r] = sv[r] * inv;
    __syncwarp();

    const float* vb = v + (size_t)b * N * D;
    float o0 = 0.0f, o1 = 0.0f;
    #pragma unroll 4
    for (int jj = 0; jj < N; jj++) {
        float pj = psm[w][jj];
        o0 = fmaf(pj, __ldg(vb + jj * D + lane),      o0);
        o1 = fmaf(pj, __ldg(vb + jj * D + lane + 32), o1);
    }
    float* op = out + ((size_t)b * N + i) * D;
    op[lane]      = o0;
    op[lane + 32] = o1;
}

extern "C" void kernel_launch(void* const* d_in, const int* in_sizes, int n_in,
                              void* d_out, int out_size)
{
    const float* q = (const float*)d_in[0];
    const float* k = (const float*)d_in[1];
    const float* v = (const float*)d_in[2];
    const float* m = (const float*)d_in[3];
    float* out = (float*)d_out;

    const int body = B * N * D;                 // 2,097,152 floats of `out`
    const int has_l0 = (out_size > body) ? out_size : 0;

    if (has_l0) init_l0_kernel<<<1, 1>>>(out, out_size);
    score_kernel<<<N * N, 256>>>(q, k, m, out, has_l0);
    softmax_av_kernel<<<(B * N) / 4, 128>>>(v, out);
}

// round 16
// speedup vs baseline: 1.9005x; 1.9005x over previous
#include <cuda_runtime.h>
#include <cuda_bf16.h>

#define B 256
#define N 128
#define D 64
#define TI 2
#define TJ 4
#define PITCH 72   // bf16 elems per smem row (144B = 36 banks -> conflict-free frags)

// scratch
__device__ float g_score[(size_t)B * N * N];   // [b][i][j], correction part only
__device__ float g_sq[B * N];                  // row sums of q
__device__ float g_sk[B * N];                  // row sums of k

__device__ __forceinline__ float sigmoidf_(float x) {
    return 1.0f / (1.0f + __expf(-x));
}
#define L0_SHIFT 1.5985968919582645f   // -BETA*log(-GAMMA/ZETA)

__global__ void init_l0_kernel(float* out, int out_size) {
    out[out_size - 1] = 0.0f;
}

// one warp per row: g_sq[b,i] = sum_d q ; g_sk[b,j] = sum_e k
__global__ void rowsum_kernel(const float* __restrict__ q, const float* __restrict__ k)
{
    int warp = (blockIdx.x * blockDim.x + threadIdx.x) >> 5;
    int lane = threadIdx.x & 31;
    const float* src; float* dst; int row;
    if (warp < B * N) { src = q; dst = g_sq; row = warp; }
    else              { src = k; dst = g_sk; row = warp - B * N; }
    float s = src[(size_t)row * D + lane] + src[(size_t)row * D + lane + 32];
    #pragma unroll
    for (int o = 16; o; o >>= 1) s += __shfl_xor_sync(0xFFFFFFFFu, s, o);
    if (lane == 0) dst[row] = s;
}

__device__ __forceinline__ void mma_bf16(float c[4], const unsigned a[4], const unsigned b[2]) {
    asm volatile(
        "mma.sync.aligned.m16n8k16.row.col.f32.bf16.bf16.f32 "
        "{%0,%1,%2,%3}, {%4,%5,%6,%7}, {%8,%9}, {%0,%1,%2,%3};\n"
        : "+f"(c[0]), "+f"(c[1]), "+f"(c[2]), "+f"(c[3])
        : "r"(a[0]), "r"(a[1]), "r"(a[2]), "r"(a[3]), "r"(b[0]), "r"(b[1]));
}

__device__ __forceinline__ unsigned pack_bf16x2(float lo, float hi) {
    __nv_bfloat162 h;
    h.x = __float2bfloat16_rn(lo);
    h.y = __float2bfloat16_rn(hi);
    return *(unsigned*)&h;
}

// Block = (i-pair, 4 j's). Per j: C[b,(i,d)] = sum_e k_bf16[b,e] * dZ_bf16[(i,d),e]
// via mma.sync, then epilogue: score_corr[b,i] = sum_d q[b,i,d]*C.
__global__ void __launch_bounds__(256, 1)
score_kernel(const float* __restrict__ q,
             const float* __restrict__ k,
             const float* __restrict__ m,
             float* __restrict__ out, int l0_size)
{
    extern __shared__ __nv_bfloat16 sm[];
    __nv_bfloat16* q_s = sm;                        // [TI][B][PITCH]
    __nv_bfloat16* k_s = sm + TI * B * PITCH;       // [B][PITCH]
    __nv_bfloat16* z_s = k_s + B * PITCH;           // [TI*64][PITCH]
    __shared__ float l0red[8];

    const int t    = threadIdx.x;
    const int w    = t >> 5;
    const int lane = t & 31;
    const int gid  = lane >> 2;   // group id (0..7)
    const int ctg  = lane & 3;    // thread-in-group
    const int i0 = blockIdx.x * TI;
    const int j0 = blockIdx.y * TJ;

    // ---- stage q (TI rows per b) into bf16 smem ----
    #pragma unroll
    for (int i_l = 0; i_l < TI; i_l++) {
        #pragma unroll 4
        for (int r = 0; r < 16; r++) {
            int idx = t + 256 * r;          // 4096 float4
            int b   = idx >> 4;
            int c   = idx & 15;
            float4 f = __ldg(((const float4*)q) + (size_t)b * (N * D / 4) + (i0 + i_l) * 16 + c);
            __nv_bfloat16* dst = q_s + (size_t)i_l * B * PITCH + b * PITCH + 4 * c;
            *(unsigned*)(dst)     = pack_bf16x2(f.x, f.y);
            *(unsigned*)(dst + 2) = pack_bf16x2(f.z, f.w);
        }
    }
    float l0p = 0.0f;
    __syncthreads();

    for (int jj = 0; jj < TJ; jj++) {
        const int j = j0 + jj;
        __syncthreads();   // previous GEMM done before overwriting k_s/z_s

        // ---- stage k_j ----
        #pragma unroll 4
        for (int r = 0; r < 16; r++) {
            int idx = t + 256 * r;
            int b   = idx >> 4;
            int c   = idx & 15;
            float4 f = __ldg(((const float4*)k) + (size_t)b * (N * D / 4) + j * 16 + c);
            __nv_bfloat16* dst = k_s + b * PITCH + 4 * c;
            *(unsigned*)(dst)     = pack_bf16x2(f.x, f.y);
            *(unsigned*)(dst + 2) = pack_bf16x2(f.z, f.w);
        }

        // ---- stage dZ = z - 0.5 for TI i's, plus l0 partial ----
        #pragma unroll 2
        for (int r = 0; r < 8; r++) {
            int idx = t + 256 * r;          // 2048 float4 (TI*1024)
            int i_l = idx >> 10;
            int l   = idx & 1023;
            int d   = l >> 4;
            int e4  = (l & 15) * 4;
            float4 mv = __ldg(((const float4*)m) +
                              ((size_t)(i0 + i_l) * N + j) * (D * D / 4) + l);
            l0p += sigmoidf_(mv.x + L0_SHIFT) + sigmoidf_(mv.y + L0_SHIFT)
                 + sigmoidf_(mv.z + L0_SHIFT) + sigmoidf_(mv.w + L0_SHIFT);
            float dx = fminf(fmaxf(sigmoidf_(mv.x) * 1.2f - 0.1f, 0.0f), 1.0f) - 0.5f;
            float dy = fminf(fmaxf(sigmoidf_(mv.y) * 1.2f - 0.1f, 0.0f), 1.0f) - 0.5f;
            float dz = fminf(fmaxf(sigmoidf_(mv.z) * 1.2f - 0.1f, 0.0f), 1.0f) - 0.5f;
            float dw = fminf(fmaxf(sigmoidf_(mv.w) * 1.2f - 0.1f, 0.0f), 1.0f) - 0.5f;
            __nv_bfloat16* dst = z_s + (i_l * 64 + d) * PITCH + e4;
            *(unsigned*)(dst)     = pack_bf16x2(dx, dy);
            *(unsigned*)(dst + 2) = pack_bf16x2(dz, dw);
        }
        __syncthreads();

        // ---- GEMM: warp tile 32(b) x 128(i,d), K=64 ----
        float acc[2][16][4];
        #pragma unroll
        for (int mt = 0; mt < 2; mt++)
            #pragma unroll
            for (int nf = 0; nf < 16; nf++)
                #pragma unroll
                for (int c = 0; c < 4; c++) acc[mt][nf][c] = 0.0f;

        #pragma unroll
        for (int kk = 0; kk < 4; kk++) {
            const int e0 = kk * 16 + 2 * ctg;
            unsigned a[2][4];
            #pragma unroll
            for (int mt = 0; mt < 2; mt++) {
                int r0 = w * 32 + mt * 16 + gid;
                a[mt][0] = *(const unsigned*)(k_s + r0 * PITCH + e0);
                a[mt][1] = *(const unsigned*)(k_s + (r0 + 8) * PITCH + e0);
                a[mt][2] = *(const unsigned*)(k_s + r0 * PITCH + e0 + 8);
                a[mt][3] = *(const unsigned*)(k_s + (r0 + 8) * PITCH + e0 + 8);
            }
            #pragma unroll
            for (int nf = 0; nf < 16; nf++) {
                unsigned bb[2];
                int col = nf * 8 + gid;
                bb[0] = *(const unsigned*)(z_s + col * PITCH + e0);
                bb[1] = *(const unsigned*)(z_s + col * PITCH + e0 + 8);
                mma_bf16(acc[0][nf], a[0], bb);
                mma_bf16(acc[1][nf], a[1], bb);
            }
        }

        // ---- epilogue: score_corr[b,i] = sum_d q[b,i,d] * C[b,(i,d)] ----
        #pragma unroll
        for (int i_l = 0; i_l < TI; i_l++) {
            #pragma unroll
            for (int mt = 0; mt < 2; mt++) {
                #pragma unroll
                for (int h = 0; h < 2; h++) {
                    int b = w * 32 + mt * 16 + gid + h * 8;
                    float s = 0.0f;
                    #pragma unroll
                    for (int nfl = 0; nfl < 8; nfl++) {
                        unsigned qp = *(const unsigned*)(q_s + (size_t)i_l * B * PITCH +
                                                         b * PITCH + nfl * 8 + 2 * ctg);
                        __nv_bfloat162 qv = *(__nv_bfloat162*)&qp;
                        s += __bfloat162float(qv.x) * acc[mt][i_l * 8 + nfl][h * 2 + 0]
                           + __bfloat162float(qv.y) * acc[mt][i_l * 8 + nfl][h * 2 + 1];
                    }
                    s += __shfl_xor_sync(0xFFFFFFFFu, s, 1);
                    s += __shfl_xor_sync(0xFFFFFFFFu, s, 2);
                    if (ctg == 0)
                        g_score[((size_t)b * N + (i0 + i_l)) * N + j] = s * 0.125f;
                }
            }
        }
    }

    // ---- l0 reduction: each m element touched exactly once by this grid ----
    #pragma unroll
    for (int o = 16; o; o >>= 1) l0p += __shfl_xor_sync(0xFFFFFFFFu, l0p, o);
    if (lane == 0) l0red[w] = l0p;
    __syncthreads();
    if (t == 0 && l0_size > 0) {
        float s = 0.0f;
        #pragma unroll
        for (int ww = 0; ww < 8; ww++) s += l0red[ww];
        atomicAdd(out + (l0_size - 1), s);
    }
}

// one warp per (b,i): add exact rank-1 mean term, softmax, attn @ v
__global__ void __launch_bounds__(128)
softmax_av_kernel(const float* __restrict__ v, float* __restrict__ out)
{
    const int warp = blockIdx.x * 4 + (threadIdx.x >> 5);
    const int lane = threadIdx.x & 31;
    const int w    = threadIdx.x >> 5;
    const int b = warp >> 7;
    const int i = warp & (N - 1);

    const float* s = g_score + ((size_t)b * N + i) * N;
    const float sqv = g_sq[b * N + i] * 0.0625f;     // 0.5 / sqrt(64)
    const float* skp = g_sk + b * N;

    float sv[4];
    float mx = -1e30f;
    #pragma unroll
    for (int r = 0; r < 4; r++) {
        sv[r] = s[lane + 32 * r] + sqv * skp[lane + 32 * r];
        mx = fmaxf(mx, sv[r]);
    }
    #pragma unroll
    for (int o = 16; o; o >>= 1) mx = fmaxf(mx, __shfl_xor_sync(0xFFFFFFFFu, mx, o));
    float sum = 0.0f;
    #pragma unroll
    for (int r = 0; r < 4; r++) { sv[r] = __expf(sv[r] - mx); sum += sv[r]; }
    #pragma unroll
    for (int o = 16; o; o >>= 1) sum += __shfl_xor_sync(0xFFFFFFFFu, sum, o);
    const float inv = 1.0f / sum;

    __shared__ float psm[4][N];
    #pragma unroll
    for (int r = 0; r < 4; r++) psm[w][lane + 32 * r] = sv[r] * inv;
    __syncwarp();

    const float* vb = v + (size_t)b * N * D;
    float o0 = 0.0f, o1 = 0.0f;
    #pragma unroll 4
    for (int jj = 0; jj < N; jj++) {
        float pj = psm[w][jj];
        o0 = fmaf(pj, __ldg(vb + jj * D + lane),      o0);
        o1 = fmaf(pj, __ldg(vb + jj * D + lane + 32), o1);
    }
    float* op = out + ((size_t)b * N + i) * D;
    op[lane]      = o0;
    op[lane + 32] = o1;
}

extern "C" void kernel_launch(void* const* d_in, const int* in_sizes, int n_in,
                              void* d_out, int out_size)
{
    const float* q = (const float*)d_in[0];
    const float* k = (const float*)d_in[1];
    const float* v = (const float*)d_in[2];
    const float* m = (const float*)d_in[3];
    float* out = (float*)d_out;

    const int body = B * N * D;
    const int has_l0 = (out_size > body) ? out_size : 0;

    static const int SMEM_BYTES = (TI * B + B + TI * 64) * PITCH * sizeof(__nv_bfloat16);
    cudaFuncSetAttribute(score_kernel, cudaFuncAttributeMaxDynamicSharedMemorySize, SMEM_BYTES);

    if (has_l0) init_l0_kernel<<<1, 1>>>(out, out_size);
    rowsum_kernel<<<(2 * B * N * 32) / 256, 256>>>(q, k);
    score_kernel<<<dim3(N / TI, N / TJ), 256, SMEM_BYTES>>>(q, k, m, out, has_l0);
    softmax_av_kernel<<<(B * N) / 4, 128>>>(v, out);
}